// round 10
// baseline (speedup 1.0000x reference)
#include <cuda_runtime.h>
#include <cuda_bf16.h>
#include <cstdint>
#include <math.h>

#define B_  4
#define T_  2048
#define D_  1024
#define H_  16
#define HD_ 64
#define BT_ (B_ * T_)            // 8192
#define QKV_N (3 * D_)           // 3072

// ---------------------------------------------------------------------------
// Scratch (allocation-free rule: __device__ globals)
// ---------------------------------------------------------------------------
__device__ __nv_bfloat16 g_qkvh[(size_t)BT_ * QKV_N];
__device__ __nv_bfloat16 g_qkvl[(size_t)BT_ * QKV_N];
__device__ __nv_bfloat16 g_xh[(size_t)BT_ * D_];
__device__ __nv_bfloat16 g_xl[(size_t)BT_ * D_];
__device__ __nv_bfloat16 g_ah[(size_t)BT_ * D_];
__device__ __nv_bfloat16 g_al[(size_t)BT_ * D_];
__device__ __nv_bfloat16 g_wqh[(size_t)QKV_N * D_];
__device__ __nv_bfloat16 g_wql[(size_t)QKV_N * D_];
__device__ __nv_bfloat16 g_woh[(size_t)D_ * D_];
__device__ __nv_bfloat16 g_wol[(size_t)D_ * D_];

// ---------------------------------------------------------------------------
// helpers (sm_80-level PTX, valid at sm_103)
// ---------------------------------------------------------------------------
__device__ __forceinline__ uint32_t smem_u32(const void* p) {
    uint32_t a;
    asm("{ .reg .u64 t; cvta.to.shared.u64 t, %1; cvt.u32.u64 %0, t; }"
        : "=r"(a) : "l"(p));
    return a;
}
__device__ __forceinline__ void ldmatrix_x4(uint32_t* r, uint32_t addr) {
    asm volatile("ldmatrix.sync.aligned.m8n8.x4.shared.b16 {%0,%1,%2,%3}, [%4];"
        : "=r"(r[0]), "=r"(r[1]), "=r"(r[2]), "=r"(r[3]) : "r"(addr));
}
__device__ __forceinline__ void ldmatrix_x2(uint32_t* r, uint32_t addr) {
    asm volatile("ldmatrix.sync.aligned.m8n8.x2.shared.b16 {%0,%1}, [%2];"
        : "=r"(r[0]), "=r"(r[1]) : "r"(addr));
}
__device__ __forceinline__ void ldmatrix_x2_trans(uint32_t* r, uint32_t addr) {
    asm volatile("ldmatrix.sync.aligned.m8n8.x2.trans.shared.b16 {%0,%1}, [%2];"
        : "=r"(r[0]), "=r"(r[1]) : "r"(addr));
}
__device__ __forceinline__ void mma_bf16(float* c, const uint32_t* a, const uint32_t* b) {
    asm volatile(
        "mma.sync.aligned.m16n8k16.row.col.f32.bf16.bf16.f32 "
        "{%0,%1,%2,%3}, {%4,%5,%6,%7}, {%8,%9}, {%0,%1,%2,%3};"
        : "+f"(c[0]), "+f"(c[1]), "+f"(c[2]), "+f"(c[3])
        : "r"(a[0]), "r"(a[1]), "r"(a[2]), "r"(a[3]), "r"(b[0]), "r"(b[1]));
}
__device__ __forceinline__ void cp16(uint32_t dst, const void* src) {
    asm volatile("cp.async.cg.shared.global [%0], [%1], 16;" :: "r"(dst), "l"(src));
}
__device__ __forceinline__ void cp_commit() {
    asm volatile("cp.async.commit_group;" ::: "memory");
}
__device__ __forceinline__ void cp_wait1() {
    asm volatile("cp.async.wait_group 1;" ::: "memory");
}
__device__ __forceinline__ __nv_bfloat162 split_hi2(float a, float b,
                                                    __nv_bfloat16& ha, __nv_bfloat16& hb) {
    ha = __float2bfloat16(a); hb = __float2bfloat16(b);
    return __halves2bfloat162(ha, hb);
}

// ---------------------------------------------------------------------------
// Split fp32 -> bf16 hi/lo
// ---------------------------------------------------------------------------
__global__ __launch_bounds__(256) void convert_split_kernel(
    const float* __restrict__ in, __nv_bfloat16* __restrict__ hi,
    __nv_bfloat16* __restrict__ lo, int n4)
{
    int i = blockIdx.x * blockDim.x + threadIdx.x;
    if (i >= n4) return;
    float4 v = ((const float4*)in)[i];
    __nv_bfloat16 h0 = __float2bfloat16(v.x);
    __nv_bfloat16 h1 = __float2bfloat16(v.y);
    __nv_bfloat16 h2 = __float2bfloat16(v.z);
    __nv_bfloat16 h3 = __float2bfloat16(v.w);
    __nv_bfloat162* hp = (__nv_bfloat162*)hi;
    __nv_bfloat162* lp = (__nv_bfloat162*)lo;
    hp[2 * i]     = __halves2bfloat162(h0, h1);
    hp[2 * i + 1] = __halves2bfloat162(h2, h3);
    lp[2 * i]     = __halves2bfloat162(
        __float2bfloat16(v.x - __bfloat162float(h0)),
        __float2bfloat16(v.y - __bfloat162float(h1)));
    lp[2 * i + 1] = __halves2bfloat162(
        __float2bfloat16(v.z - __bfloat162float(h2)),
        __float2bfloat16(v.w - __bfloat162float(h3)));
}

// ---------------------------------------------------------------------------
// Transpose W[K,N] fp32 -> Bh/Bl[N,K] bf16 (hi/lo split)
// ---------------------------------------------------------------------------
__global__ __launch_bounds__(256) void transpose_split_kernel(
    const float* __restrict__ w, __nv_bfloat16* __restrict__ bh,
    __nv_bfloat16* __restrict__ bl, int K, int N)
{
    __shared__ float t[32][33];
    const int n0 = blockIdx.x * 32;
    const int k0 = blockIdx.y * 32;
    const int tx = threadIdx.x;
    const int ty = threadIdx.y;
#pragma unroll
    for (int i = 0; i < 32; i += 8)
        t[ty + i][tx] = w[(size_t)(k0 + ty + i) * N + n0 + tx];
    __syncthreads();
#pragma unroll
    for (int i = 0; i < 32; i += 8) {
        float v = t[tx][ty + i];
        __nv_bfloat16 h = __float2bfloat16(v);
        __nv_bfloat16 l = __float2bfloat16(v - __bfloat162float(h));
        bh[(size_t)(n0 + ty + i) * K + k0 + tx] = h;
        bl[(size_t)(n0 + ty + i) * K + k0 + tx] = l;
    }
}

// ---------------------------------------------------------------------------
// HMMA GEMM, cp.async 2-stage, 256 threads (8 warps).
// CTA tile 256x128, warp tile 64x64 (wr=wid>>1 in M, wc=wid&1 in N).
// B fragments via paired ldmatrix.x4 (n16k16 per instruction).
// 3-term bf16 split: AhBh + AhBl + AlBh, fp32 accum.
// ---------------------------------------------------------------------------
#define MBM 256
#define MBN 128
#define MBK 64
#define MSTRIDE 72
#define ATILE_E (256 * MSTRIDE)
#define BTILE_E (128 * MSTRIDE)
#define MSTG_E  (2 * ATILE_E + 2 * BTILE_E)
#define MSMEM_TOTAL (2 * MSTG_E * 2)     // 221184 bytes

template <bool SPLIT_OUT>
__global__ __launch_bounds__(256, 1) void hmma_gemm_kernel(
    const __nv_bfloat16* __restrict__ Ah, const __nv_bfloat16* __restrict__ Al,
    const __nv_bfloat16* __restrict__ Bh, const __nv_bfloat16* __restrict__ Bl,
    float* __restrict__ C,
    __nv_bfloat16* __restrict__ Ch, __nv_bfloat16* __restrict__ Cl,
    int M, int N, int K)
{
    extern __shared__ __nv_bfloat16 sm[];
    const uint32_t sm_u = smem_u32(sm);

    const int tid = threadIdx.x;
    const int wid = tid >> 5;
    const int lid = tid & 31;
    const int bm  = blockIdx.y * MBM;
    const int bn  = blockIdx.x * MBN;
    const int wr  = wid >> 1;            // 0..3 -> m offset wr*64
    const int wc  = wid & 1;             // 0..1 -> n offset wc*64

    float c[4][8][4];
#pragma unroll
    for (int mi = 0; mi < 4; mi++)
#pragma unroll
        for (int ni = 0; ni < 8; ni++)
#pragma unroll
            for (int k = 0; k < 4; k++) c[mi][ni][k] = 0.0f;

    // cp.async mapping: rows r0+32i, 16B column c16
    const int r0  = tid >> 3;            // 0..31
    const int c16 = tid & 7;
    const uint32_t sm_off = (uint32_t)(r0 * 144 + c16 * 16);

    const __nv_bfloat16* gA[2] = {
        Ah + (size_t)(bm + r0) * K + c16 * 8,
        Al + (size_t)(bm + r0) * K + c16 * 8 };
    const __nv_bfloat16* gB[2] = {
        Bh + (size_t)(bn + r0) * K + c16 * 8,
        Bl + (size_t)(bn + r0) * K + c16 * 8 };

    auto issue_chunk = [&](int ch, int stage) {
        const uint32_t sbase = sm_u + (uint32_t)stage * (MSTG_E * 2);
        const int k0 = ch * MBK;
#pragma unroll
        for (int t = 0; t < 2; t++) {
            const __nv_bfloat16* g = gA[t] + k0;
            const uint32_t sb = sbase + (uint32_t)t * (ATILE_E * 2) + sm_off;
#pragma unroll
            for (int i = 0; i < 8; i++)
                cp16(sb + (uint32_t)i * (32 * 144), g + (size_t)(32 * i) * K);
        }
#pragma unroll
        for (int t = 0; t < 2; t++) {
            const __nv_bfloat16* g = gB[t] + k0;
            const uint32_t sb = sbase + (uint32_t)(2 * ATILE_E + t * BTILE_E) * 2 + sm_off;
#pragma unroll
            for (int i = 0; i < 4; i++)
                cp16(sb + (uint32_t)i * (32 * 144), g + (size_t)(32 * i) * K);
        }
    };

    // ldmatrix offsets (elements -> bytes)
    const int a_row = wr * 64 + (lid & 15);
    const int a_col = (lid >> 4) * 8;
    const uint32_t a_off = (uint32_t)(a_row * MSTRIDE + a_col) * 2;
    // B x4: lanes 0-7 -> (n0-7,k0), 8-15 -> (n0-7,k8), 16-23 -> (n8-15,k0), 24-31 -> (n8-15,k8)
    const int b_row = wc * 64 + (lid & 7) + ((lid >> 4) & 1) * 8;
    const int b_col = ((lid >> 3) & 1) * 8;
    const uint32_t b_off = (uint32_t)(b_row * MSTRIDE + b_col) * 2;

    const int nch = K / MBK;
    issue_chunk(0, 0);
    cp_commit();

    for (int ch = 0; ch < nch; ch++) {
        const int s = ch & 1;
        if (ch + 1 < nch) issue_chunk(ch + 1, s ^ 1);
        cp_commit();
        cp_wait1();
        __syncthreads();

        const uint32_t st = sm_u + (uint32_t)s * (MSTG_E * 2);
        const uint32_t uAh = st;
        const uint32_t uAl = st + ATILE_E * 2;
        const uint32_t uBh = st + 2 * ATILE_E * 2;
        const uint32_t uBl = st + (2 * ATILE_E + BTILE_E) * 2;

#pragma unroll
        for (int kk = 0; kk < MBK; kk += 16) {
            uint32_t af[4][4], bh4[4][4];
            // Ah fragments, Bh fragments (paired x4)
#pragma unroll
            for (int mi = 0; mi < 4; mi++)
                ldmatrix_x4(af[mi], uAh + a_off + (uint32_t)(mi * 16 * MSTRIDE + kk) * 2);
#pragma unroll
            for (int p = 0; p < 4; p++)
                ldmatrix_x4(bh4[p], uBh + b_off + (uint32_t)(p * 16 * MSTRIDE + kk) * 2);
#pragma unroll
            for (int mi = 0; mi < 4; mi++)
#pragma unroll
                for (int p = 0; p < 4; p++) {
                    mma_bf16(c[mi][2 * p],     af[mi], &bh4[p][0]);
                    mma_bf16(c[mi][2 * p + 1], af[mi], &bh4[p][2]);
                }
            // Ah x Bl
            {
                uint32_t bl4[4][4];
#pragma unroll
                for (int p = 0; p < 4; p++)
                    ldmatrix_x4(bl4[p], uBl + b_off + (uint32_t)(p * 16 * MSTRIDE + kk) * 2);
#pragma unroll
                for (int mi = 0; mi < 4; mi++)
#pragma unroll
                    for (int p = 0; p < 4; p++) {
                        mma_bf16(c[mi][2 * p],     af[mi], &bl4[p][0]);
                        mma_bf16(c[mi][2 * p + 1], af[mi], &bl4[p][2]);
                    }
            }
            // Al x Bh (reuse af regs)
#pragma unroll
            for (int mi = 0; mi < 4; mi++)
                ldmatrix_x4(af[mi], uAl + a_off + (uint32_t)(mi * 16 * MSTRIDE + kk) * 2);
#pragma unroll
            for (int mi = 0; mi < 4; mi++)
#pragma unroll
                for (int p = 0; p < 4; p++) {
                    mma_bf16(c[mi][2 * p],     af[mi], &bh4[p][0]);
                    mma_bf16(c[mi][2 * p + 1], af[mi], &bh4[p][2]);
                }
        }
        __syncthreads();
    }

    const int grp = lid >> 2;
    const int qd  = lid & 3;
#pragma unroll
    for (int mi = 0; mi < 4; mi++) {
        const int row_lo = bm + wr * 64 + mi * 16 + grp;
#pragma unroll
        for (int ni = 0; ni < 8; ni++) {
            const int col = bn + wc * 64 + ni * 8 + qd * 2;
            if (SPLIT_OUT) {
                __nv_bfloat16 h0, h1, h2, h3;
                __nv_bfloat162 hi01 = split_hi2(c[mi][ni][0], c[mi][ni][1], h0, h1);
                __nv_bfloat162 hi23 = split_hi2(c[mi][ni][2], c[mi][ni][3], h2, h3);
                *(__nv_bfloat162*)(Ch + (size_t)row_lo * N + col) = hi01;
                *(__nv_bfloat162*)(Ch + (size_t)(row_lo + 8) * N + col) = hi23;
                *(__nv_bfloat162*)(Cl + (size_t)row_lo * N + col) = __halves2bfloat162(
                    __float2bfloat16(c[mi][ni][0] - __bfloat162float(h0)),
                    __float2bfloat16(c[mi][ni][1] - __bfloat162float(h1)));
                *(__nv_bfloat162*)(Cl + (size_t)(row_lo + 8) * N + col) = __halves2bfloat162(
                    __float2bfloat16(c[mi][ni][2] - __bfloat162float(h2)),
                    __float2bfloat16(c[mi][ni][3] - __bfloat162float(h3)));
            } else {
                *(float2*)(C + (size_t)row_lo * N + col) =
                    make_float2(c[mi][ni][0], c[mi][ni][1]);
                *(float2*)(C + (size_t)(row_lo + 8) * N + col) =
                    make_float2(c[mi][ni][2], c[mi][ni][3]);
            }
        }
    }
}

// ---------------------------------------------------------------------------
// HMMA flash attention (causal) — unchanged from R9 (measured 1.66e-5 path).
// ---------------------------------------------------------------------------
#define FSTR 72
#define FQH 0
#define FQL (128 * FSTR)
#define FKH (256 * FSTR)
#define FKL (320 * FSTR)
#define FVH (384 * FSTR)
#define FVL (448 * FSTR)
#define F_SMEM_E (512 * FSTR)
#define F_SMEM_BYTES (F_SMEM_E * 2)      // 73728

__global__ __launch_bounds__(256, 2) void flash_hmma_kernel(
    const __nv_bfloat16* __restrict__ qkvh, const __nv_bfloat16* __restrict__ qkvl,
    __nv_bfloat16* __restrict__ outh, __nv_bfloat16* __restrict__ outl)
{
    extern __shared__ __nv_bfloat16 fsm[];
    const uint32_t sm_u = smem_u32(fsm);

    const int qtile = blockIdx.x;
    const int h  = blockIdx.y;
    const int b  = blockIdx.z;
    const int q0 = qtile * 128;

    const int tid = threadIdx.x;
    const int wid = tid >> 5;
    const int lid = tid & 31;
    const int grp = lid >> 2;
    const int qd  = lid & 3;
    const int w16 = wid * 16;

    const size_t base = (size_t)b * T_ * QKV_N + (size_t)h * HD_;
    const __nv_bfloat16* qh_g = qkvh + base;
    const __nv_bfloat16* ql_g = qkvl + base;
    const __nv_bfloat16* kh_g = qkvh + base + D_;
    const __nv_bfloat16* kl_g = qkvl + base + D_;
    const __nv_bfloat16* vh_g = qkvh + base + 2 * D_;
    const __nv_bfloat16* vl_g = qkvl + base + 2 * D_;

    {
#pragma unroll
        for (int i = 0; i < 4; i++) {
            const int idx = tid + i * 256;
            const int r = idx >> 3;
            const int c8 = idx & 7;
            *(uint4*)(fsm + FQH + r * FSTR + c8 * 8) =
                *(const uint4*)(qh_g + (size_t)(q0 + r) * QKV_N + c8 * 8);
            *(uint4*)(fsm + FQL + r * FSTR + c8 * 8) =
                *(const uint4*)(ql_g + (size_t)(q0 + r) * QKV_N + c8 * 8);
        }
    }

    float o[8][4];
#pragma unroll
    for (int ni = 0; ni < 8; ni++)
#pragma unroll
        for (int k = 0; k < 4; k++) o[ni][k] = 0.0f;
    float m0 = -1e30f, m1 = -1e30f, l0 = 0.0f, l1 = 0.0f;

    const uint32_t a_off = (uint32_t)((w16 + (lid & 15)) * FSTR + (lid >> 4) * 8) * 2;
    const uint32_t b_off = (uint32_t)(((lid & 7)) * FSTR + ((lid >> 3) & 1) * 8) * 2;
    const uint32_t v_off = (uint32_t)((lid & 15) * FSTR) * 2;

    const uint32_t uQH = sm_u + FQH * 2, uQL = sm_u + FQL * 2;
    const uint32_t uKH = sm_u + FKH * 2, uKL = sm_u + FKL * 2;
    const uint32_t uVH = sm_u + FVH * 2, uVL = sm_u + FVL * 2;

    const int row0_abs = q0 + w16 + grp;

    auto tile = [&](int kt, bool masked) {
        const int k0 = kt * 64;
        __syncthreads();
        {
#pragma unroll
            for (int i = 0; i < 2; i++) {
                const int idx = tid + i * 256;
                const int r = idx >> 3;
                const int c8 = idx & 7;
                const size_t go = (size_t)(k0 + r) * QKV_N + c8 * 8;
                const int so = r * FSTR + c8 * 8;
                *(uint4*)(fsm + FKH + so) = *(const uint4*)(kh_g + go);
                *(uint4*)(fsm + FKL + so) = *(const uint4*)(kl_g + go);
                *(uint4*)(fsm + FVH + so) = *(const uint4*)(vh_g + go);
                *(uint4*)(fsm + FVL + so) = *(const uint4*)(vl_g + go);
            }
        }
        __syncthreads();

        float s[8][4];
#pragma unroll
        for (int ni = 0; ni < 8; ni++)
#pragma unroll
            for (int k = 0; k < 4; k++) s[ni][k] = 0.0f;

#pragma unroll
        for (int kk4 = 0; kk4 < 4; kk4++) {
            const uint32_t ko = (uint32_t)kk4 * 32;
            uint32_t qh[4], ql[4];
            ldmatrix_x4(qh, uQH + a_off + ko);
            ldmatrix_x4(ql, uQL + a_off + ko);
#pragma unroll
            for (int ni = 0; ni < 8; ni++) {
                const uint32_t no = (uint32_t)(ni * 8 * FSTR) * 2;
                uint32_t kh[2], kl[2];
                ldmatrix_x2(kh, uKH + b_off + no + ko);
                ldmatrix_x2(kl, uKL + b_off + no + ko);
                mma_bf16(s[ni], qh, kh);
                mma_bf16(s[ni], qh, kl);
                mma_bf16(s[ni], ql, kh);
            }
        }

        const float scale = 0.125f;
#pragma unroll
        for (int ni = 0; ni < 8; ni++) {
#pragma unroll
            for (int k = 0; k < 4; k++) s[ni][k] *= scale;
            if (masked) {
                const int col = k0 + ni * 8 + qd * 2;
                if (col > row0_abs)     s[ni][0] = -1e30f;
                if (col + 1 > row0_abs) s[ni][1] = -1e30f;
                if (col > row0_abs + 8)     s[ni][2] = -1e30f;
                if (col + 1 > row0_abs + 8) s[ni][3] = -1e30f;
            }
        }

        float mx0 = -1e30f, mx1 = -1e30f;
#pragma unroll
        for (int ni = 0; ni < 8; ni++) {
            mx0 = fmaxf(mx0, fmaxf(s[ni][0], s[ni][1]));
            mx1 = fmaxf(mx1, fmaxf(s[ni][2], s[ni][3]));
        }
        mx0 = fmaxf(mx0, __shfl_xor_sync(0xffffffffu, mx0, 1));
        mx0 = fmaxf(mx0, __shfl_xor_sync(0xffffffffu, mx0, 2));
        mx1 = fmaxf(mx1, __shfl_xor_sync(0xffffffffu, mx1, 1));
        mx1 = fmaxf(mx1, __shfl_xor_sync(0xffffffffu, mx1, 2));
        const float mn0 = fmaxf(m0, mx0);
        const float mn1 = fmaxf(m1, mx1);
        const float al0 = __expf(m0 - mn0);
        const float al1 = __expf(m1 - mn1);

        uint32_t pH[8][2], pL[8][2];
        float sum0 = 0.0f, sum1 = 0.0f;
#pragma unroll
        for (int ni = 0; ni < 8; ni++) {
            float p0 = __expf(s[ni][0] - mn0);
            float p1 = __expf(s[ni][1] - mn0);
            float p2 = __expf(s[ni][2] - mn1);
            float p3 = __expf(s[ni][3] - mn1);
            sum0 += p0 + p1; sum1 += p2 + p3;
            __nv_bfloat16 h0, h1, h2, h3;
            __nv_bfloat162 ph01 = split_hi2(p0, p1, h0, h1);
            __nv_bfloat162 ph23 = split_hi2(p2, p3, h2, h3);
            __nv_bfloat162 pl01 = __halves2bfloat162(
                __float2bfloat16(p0 - __bfloat162float(h0)),
                __float2bfloat16(p1 - __bfloat162float(h1)));
            __nv_bfloat162 pl23 = __halves2bfloat162(
                __float2bfloat16(p2 - __bfloat162float(h2)),
                __float2bfloat16(p3 - __bfloat162float(h3)));
            pH[ni][0] = *(uint32_t*)&ph01; pH[ni][1] = *(uint32_t*)&ph23;
            pL[ni][0] = *(uint32_t*)&pl01; pL[ni][1] = *(uint32_t*)&pl23;
        }
        sum0 += __shfl_xor_sync(0xffffffffu, sum0, 1);
        sum0 += __shfl_xor_sync(0xffffffffu, sum0, 2);
        sum1 += __shfl_xor_sync(0xffffffffu, sum1, 1);
        sum1 += __shfl_xor_sync(0xffffffffu, sum1, 2);
        l0 = l0 * al0 + sum0;
        l1 = l1 * al1 + sum1;
        m0 = mn0; m1 = mn1;
#pragma unroll
        for (int ni = 0; ni < 8; ni++) {
            o[ni][0] *= al0; o[ni][1] *= al0;
            o[ni][2] *= al1; o[ni][3] *= al1;
        }

#pragma unroll
        for (int j = 0; j < 4; j++) {
            uint32_t ah[4] = { pH[2 * j][0], pH[2 * j][1], pH[2 * j + 1][0], pH[2 * j + 1][1] };
            uint32_t al_[4] = { pL[2 * j][0], pL[2 * j][1], pL[2 * j + 1][0], pL[2 * j + 1][1] };
            const uint32_t jo = (uint32_t)(j * 16 * FSTR) * 2;
#pragma unroll
            for (int ni = 0; ni < 8; ni++) {
                const uint32_t no = (uint32_t)(ni * 8) * 2;
                uint32_t vh[2], vl[2];
                ldmatrix_x2_trans(vh, uVH + v_off + jo + no);
                ldmatrix_x2_trans(vl, uVL + v_off + jo + no);
                mma_bf16(o[ni], ah, vh);
                mma_bf16(o[ni], al_, vh);
                mma_bf16(o[ni], ah, vl);
            }
        }
    };

    for (int kt = 0; kt < 2 * qtile; kt++) tile(kt, false);
    tile(2 * qtile, true);
    tile(2 * qtile + 1, true);

    const float inv0 = 1.0f / l0;
    const float inv1 = 1.0f / l1;
    const size_t ro0 = (size_t)(b * T_ + row0_abs) * D_ + h * HD_;
    const size_t ro1 = ro0 + (size_t)8 * D_;
#pragma unroll
    for (int ni = 0; ni < 8; ni++) {
        float v0 = o[ni][0] * inv0, v1 = o[ni][1] * inv0;
        float v2 = o[ni][2] * inv1, v3 = o[ni][3] * inv1;
        __nv_bfloat16 h0, h1, h2, h3;
        __nv_bfloat162 hi01 = split_hi2(v0, v1, h0, h1);
        __nv_bfloat162 hi23 = split_hi2(v2, v3, h2, h3);
        *(__nv_bfloat162*)(outh + ro0 + ni * 8 + qd * 2) = hi01;
        *(__nv_bfloat162*)(outh + ro1 + ni * 8 + qd * 2) = hi23;
        *(__nv_bfloat162*)(outl + ro0 + ni * 8 + qd * 2) = __halves2bfloat162(
            __float2bfloat16(v0 - __bfloat162float(h0)),
            __float2bfloat16(v1 - __bfloat162float(h1)));
        *(__nv_bfloat162*)(outl + ro1 + ni * 8 + qd * 2) = __halves2bfloat162(
            __float2bfloat16(v2 - __bfloat162float(h2)),
            __float2bfloat16(v3 - __bfloat162float(h3)));
    }
}

// ---------------------------------------------------------------------------
// kernel_launch
// ---------------------------------------------------------------------------
extern "C" void kernel_launch(void* const* d_in, const int* in_sizes, int n_in,
                              void* d_out, int out_size)
{
    const float* x     = (const float*)d_in[0];
    const float* w_qkv = (const float*)d_in[1];
    const float* w_out = (const float*)d_in[2];
    float* out = (float*)d_out;

    __nv_bfloat16 *qkvh, *qkvl, *xh, *xl, *ah, *al, *wqh, *wql, *woh, *wol;
    cudaGetSymbolAddress((void**)&qkvh, g_qkvh);
    cudaGetSymbolAddress((void**)&qkvl, g_qkvl);
    cudaGetSymbolAddress((void**)&xh,  g_xh);
    cudaGetSymbolAddress((void**)&xl,  g_xl);
    cudaGetSymbolAddress((void**)&ah,  g_ah);
    cudaGetSymbolAddress((void**)&al,  g_al);
    cudaGetSymbolAddress((void**)&wqh, g_wqh);
    cudaGetSymbolAddress((void**)&wql, g_wql);
    cudaGetSymbolAddress((void**)&woh, g_woh);
    cudaGetSymbolAddress((void**)&wol, g_wol);

    cudaFuncSetAttribute(hmma_gemm_kernel<true>,
                         cudaFuncAttributeMaxDynamicSharedMemorySize, MSMEM_TOTAL);
    cudaFuncSetAttribute(hmma_gemm_kernel<false>,
                         cudaFuncAttributeMaxDynamicSharedMemorySize, MSMEM_TOTAL);
    cudaFuncSetAttribute(flash_hmma_kernel,
                         cudaFuncAttributeMaxDynamicSharedMemorySize, F_SMEM_BYTES);

    {
        int n4 = BT_ * D_ / 4;
        convert_split_kernel<<<(n4 + 255) / 256, 256>>>(x, xh, xl, n4);
    }
    {
        dim3 bb(32, 8);
        transpose_split_kernel<<<dim3(QKV_N / 32, D_ / 32), bb>>>(w_qkv, wqh, wql, D_, QKV_N);
        transpose_split_kernel<<<dim3(D_ / 32,   D_ / 32), bb>>>(w_out, woh, wol, D_, D_);
    }
    {
        dim3 g(QKV_N / MBN, BT_ / MBM);   // (24, 32)
        hmma_gemm_kernel<true><<<g, 256, MSMEM_TOTAL>>>(
            xh, xl, wqh, wql, nullptr, qkvh, qkvl, BT_, QKV_N, D_);
    }
    {
        dim3 g(T_ / 128, H_, B_);
        flash_hmma_kernel<<<g, 256, F_SMEM_BYTES>>>(qkvh, qkvl, ah, al);
    }
    {
        dim3 g(D_ / MBN, BT_ / MBM);      // (8, 32)
        hmma_gemm_kernel<false><<<g, 256, MSMEM_TOTAL>>>(
            ah, al, woh, wol, out, nullptr, nullptr, BT_, D_, D_);
    }
}

// round 12
// speedup vs baseline: 1.0243x; 1.0243x over previous
#include <cuda_runtime.h>
#include <cuda_bf16.h>
#include <cstdint>
#include <math.h>

#define B_  4
#define T_  2048
#define D_  1024
#define H_  16
#define HD_ 64
#define BT_ (B_ * T_)            // 8192
#define QKV_N (3 * D_)           // 3072

// ---------------------------------------------------------------------------
// Scratch (allocation-free rule: __device__ globals)
// ---------------------------------------------------------------------------
__device__ __nv_bfloat16 g_qkvh[(size_t)BT_ * QKV_N];
__device__ __nv_bfloat16 g_qkvl[(size_t)BT_ * QKV_N];
__device__ __nv_bfloat16 g_xh[(size_t)BT_ * D_];
__device__ __nv_bfloat16 g_xl[(size_t)BT_ * D_];
__device__ __nv_bfloat16 g_ah[(size_t)BT_ * D_];
__device__ __nv_bfloat16 g_al[(size_t)BT_ * D_];
__device__ __nv_bfloat16 g_wqh[(size_t)QKV_N * D_];
__device__ __nv_bfloat16 g_wql[(size_t)QKV_N * D_];
__device__ __nv_bfloat16 g_woh[(size_t)D_ * D_];
__device__ __nv_bfloat16 g_wol[(size_t)D_ * D_];

// ---------------------------------------------------------------------------
// helpers (sm_80-level PTX, valid at sm_103)
// ---------------------------------------------------------------------------
__device__ __forceinline__ uint32_t smem_u32(const void* p) {
    uint32_t a;
    asm("{ .reg .u64 t; cvta.to.shared.u64 t, %1; cvt.u32.u64 %0, t; }"
        : "=r"(a) : "l"(p));
    return a;
}
__device__ __forceinline__ void ldmatrix_x4(uint32_t* r, uint32_t addr) {
    asm volatile("ldmatrix.sync.aligned.m8n8.x4.shared.b16 {%0,%1,%2,%3}, [%4];"
        : "=r"(r[0]), "=r"(r[1]), "=r"(r[2]), "=r"(r[3]) : "r"(addr));
}
__device__ __forceinline__ void ldmatrix_x2(uint32_t* r, uint32_t addr) {
    asm volatile("ldmatrix.sync.aligned.m8n8.x2.shared.b16 {%0,%1}, [%2];"
        : "=r"(r[0]), "=r"(r[1]) : "r"(addr));
}
__device__ __forceinline__ void ldmatrix_x2_trans(uint32_t* r, uint32_t addr) {
    asm volatile("ldmatrix.sync.aligned.m8n8.x2.trans.shared.b16 {%0,%1}, [%2];"
        : "=r"(r[0]), "=r"(r[1]) : "r"(addr));
}
__device__ __forceinline__ void mma_bf16(float* c, const uint32_t* a, const uint32_t* b) {
    asm volatile(
        "mma.sync.aligned.m16n8k16.row.col.f32.bf16.bf16.f32 "
        "{%0,%1,%2,%3}, {%4,%5,%6,%7}, {%8,%9}, {%0,%1,%2,%3};"
        : "+f"(c[0]), "+f"(c[1]), "+f"(c[2]), "+f"(c[3])
        : "r"(a[0]), "r"(a[1]), "r"(a[2]), "r"(a[3]), "r"(b[0]), "r"(b[1]));
}
__device__ __forceinline__ void cp16(uint32_t dst, const void* src) {
    asm volatile("cp.async.cg.shared.global [%0], [%1], 16;" :: "r"(dst), "l"(src));
}
__device__ __forceinline__ void cp_commit() {
    asm volatile("cp.async.commit_group;" ::: "memory");
}
__device__ __forceinline__ void cp_wait1() {
    asm volatile("cp.async.wait_group 1;" ::: "memory");
}
__device__ __forceinline__ __nv_bfloat162 split_hi2(float a, float b,
                                                    __nv_bfloat16& ha, __nv_bfloat16& hb) {
    ha = __float2bfloat16(a); hb = __float2bfloat16(b);
    return __halves2bfloat162(ha, hb);
}

// ---------------------------------------------------------------------------
// Split fp32 -> bf16 hi/lo
// ---------------------------------------------------------------------------
__global__ __launch_bounds__(256) void convert_split_kernel(
    const float* __restrict__ in, __nv_bfloat16* __restrict__ hi,
    __nv_bfloat16* __restrict__ lo, int n4)
{
    int i = blockIdx.x * blockDim.x + threadIdx.x;
    if (i >= n4) return;
    float4 v = ((const float4*)in)[i];
    __nv_bfloat16 h0 = __float2bfloat16(v.x);
    __nv_bfloat16 h1 = __float2bfloat16(v.y);
    __nv_bfloat16 h2 = __float2bfloat16(v.z);
    __nv_bfloat16 h3 = __float2bfloat16(v.w);
    __nv_bfloat162* hp = (__nv_bfloat162*)hi;
    __nv_bfloat162* lp = (__nv_bfloat162*)lo;
    hp[2 * i]     = __halves2bfloat162(h0, h1);
    hp[2 * i + 1] = __halves2bfloat162(h2, h3);
    lp[2 * i]     = __halves2bfloat162(
        __float2bfloat16(v.x - __bfloat162float(h0)),
        __float2bfloat16(v.y - __bfloat162float(h1)));
    lp[2 * i + 1] = __halves2bfloat162(
        __float2bfloat16(v.z - __bfloat162float(h2)),
        __float2bfloat16(v.w - __bfloat162float(h3)));
}

// ---------------------------------------------------------------------------
// Transpose W[K,N] fp32 -> Bh/Bl[N,K] bf16 (hi/lo split)
// ---------------------------------------------------------------------------
__global__ __launch_bounds__(256) void transpose_split_kernel(
    const float* __restrict__ w, __nv_bfloat16* __restrict__ bh,
    __nv_bfloat16* __restrict__ bl, int K, int N)
{
    __shared__ float t[32][33];
    const int n0 = blockIdx.x * 32;
    const int k0 = blockIdx.y * 32;
    const int tx = threadIdx.x;
    const int ty = threadIdx.y;
#pragma unroll
    for (int i = 0; i < 32; i += 8)
        t[ty + i][tx] = w[(size_t)(k0 + ty + i) * N + n0 + tx];
    __syncthreads();
#pragma unroll
    for (int i = 0; i < 32; i += 8) {
        float v = t[tx][ty + i];
        __nv_bfloat16 h = __float2bfloat16(v);
        __nv_bfloat16 l = __float2bfloat16(v - __bfloat162float(h));
        bh[(size_t)(n0 + ty + i) * K + k0 + tx] = h;
        bl[(size_t)(n0 + ty + i) * K + k0 + tx] = l;
    }
}

// ---------------------------------------------------------------------------
// HMMA GEMM, cp.async 2-stage, 256 threads (8 warps), warp tile 64x32.
// BK=32 -> 80KB smem/CTA -> 2 CTAs/SM (4 warps/SMSP for latency hiding).
// cp.async mapping (FIXED): 128 rows x 4 16B-cols = 512 chunks/tile;
// each thread loads rows r0 and r0+64 -> 2 chunks/tile.
// 3-term bf16 split: AhBh + AhBl + AlBh, fp32 accum.
// ---------------------------------------------------------------------------
#define MBM 128
#define MBN 128
#define MBK 32
#define MSTRIDE 40                        // 32 + 8 pad (80B rows, conflict-free)
#define MTILE_E (128 * MSTRIDE)           // 5120 elems
#define MSTG_E  (4 * MTILE_E)             // Ah|Al|Bh|Bl per stage
#define MSMEM_TOTAL (2 * MSTG_E * 2)      // 81920 bytes

template <bool SPLIT_OUT>
__global__ __launch_bounds__(256, 2) void hmma_gemm_kernel(
    const __nv_bfloat16* __restrict__ Ah, const __nv_bfloat16* __restrict__ Al,
    const __nv_bfloat16* __restrict__ Bh, const __nv_bfloat16* __restrict__ Bl,
    float* __restrict__ C,
    __nv_bfloat16* __restrict__ Ch, __nv_bfloat16* __restrict__ Cl,
    int M, int N, int K)
{
    extern __shared__ __nv_bfloat16 sm[];
    const uint32_t sm_u = smem_u32(sm);

    const int tid = threadIdx.x;
    const int wid = tid >> 5;
    const int lid = tid & 31;
    const int bm  = blockIdx.y * MBM;
    const int bn  = blockIdx.x * MBN;
    const int wr  = wid >> 2;
    const int wc  = wid & 3;

    float c[4][4][4];
#pragma unroll
    for (int mi = 0; mi < 4; mi++)
#pragma unroll
        for (int ni = 0; ni < 4; ni++)
#pragma unroll
            for (int k = 0; k < 4; k++) c[mi][ni][k] = 0.0f;

    // cp.async mapping: rows r0 and r0+64, 16B column c16 (4 cols = 64B row)
    const int r0  = tid >> 2;             // 0..63
    const int c16 = tid & 3;              // 0..3
    const uint32_t sm_off = (uint32_t)(r0 * 80 + c16 * 16);

    const __nv_bfloat16* gsrc[4] = {
        Ah + (size_t)(bm + r0) * K + c16 * 8,
        Al + (size_t)(bm + r0) * K + c16 * 8,
        Bh + (size_t)(bn + r0) * K + c16 * 8,
        Bl + (size_t)(bn + r0) * K + c16 * 8 };

    auto issue_chunk = [&](int ch, int stage) {
        const uint32_t sbase = sm_u + (uint32_t)stage * (MSTG_E * 2);
        const int k0 = ch * MBK;
#pragma unroll
        for (int t = 0; t < 4; t++) {
            const __nv_bfloat16* g = gsrc[t] + k0;
            const uint32_t sb = sbase + (uint32_t)t * (MTILE_E * 2) + sm_off;
            cp16(sb, g);
            cp16(sb + (uint32_t)(64 * 80), g + (size_t)64 * K);
        }
    };

    const int a_row = wr * 64 + (lid & 15);
    const int a_col = (lid >> 4) * 8;
    const int b_row = wc * 32 + (lid & 7);
    const int b_col = ((lid >> 3) & 1) * 8;
    const uint32_t a_off = (uint32_t)(a_row * MSTRIDE + a_col) * 2;
    const uint32_t b_off = (uint32_t)(b_row * MSTRIDE + b_col) * 2;

    const int nch = K / MBK;
    issue_chunk(0, 0);
    cp_commit();

    for (int ch = 0; ch < nch; ch++) {
        const int s = ch & 1;
        if (ch + 1 < nch) issue_chunk(ch + 1, s ^ 1);
        cp_commit();
        cp_wait1();
        __syncthreads();

        const uint32_t st = sm_u + (uint32_t)s * (MSTG_E * 2);
        const uint32_t uAh = st;
        const uint32_t uAl = st + MTILE_E * 2;
        const uint32_t uBh = st + 2 * MTILE_E * 2;
        const uint32_t uBl = st + 3 * MTILE_E * 2;

#pragma unroll
        for (int kk = 0; kk < MBK; kk += 16) {
            uint32_t af[4][4], bf[4][2];
#pragma unroll
            for (int mi = 0; mi < 4; mi++)
                ldmatrix_x4(af[mi], uAh + a_off + (uint32_t)(mi * 16 * MSTRIDE + kk) * 2);
#pragma unroll
            for (int ni = 0; ni < 4; ni++)
                ldmatrix_x2(bf[ni], uBh + b_off + (uint32_t)(ni * 8 * MSTRIDE + kk) * 2);
#pragma unroll
            for (int mi = 0; mi < 4; mi++)
#pragma unroll
                for (int ni = 0; ni < 4; ni++)
                    mma_bf16(c[mi][ni], af[mi], bf[ni]);
            uint32_t bl_[4][2];
#pragma unroll
            for (int ni = 0; ni < 4; ni++)
                ldmatrix_x2(bl_[ni], uBl + b_off + (uint32_t)(ni * 8 * MSTRIDE + kk) * 2);
#pragma unroll
            for (int mi = 0; mi < 4; mi++)
#pragma unroll
                for (int ni = 0; ni < 4; ni++)
                    mma_bf16(c[mi][ni], af[mi], bl_[ni]);
#pragma unroll
            for (int mi = 0; mi < 4; mi++)
                ldmatrix_x4(af[mi], uAl + a_off + (uint32_t)(mi * 16 * MSTRIDE + kk) * 2);
#pragma unroll
            for (int mi = 0; mi < 4; mi++)
#pragma unroll
                for (int ni = 0; ni < 4; ni++)
                    mma_bf16(c[mi][ni], af[mi], bf[ni]);
        }
        __syncthreads();
    }

    const int grp = lid >> 2;
    const int qd  = lid & 3;
#pragma unroll
    for (int mi = 0; mi < 4; mi++) {
        const int row_lo = bm + wr * 64 + mi * 16 + grp;
#pragma unroll
        for (int ni = 0; ni < 4; ni++) {
            const int col = bn + wc * 32 + ni * 8 + qd * 2;
            if (SPLIT_OUT) {
                __nv_bfloat16 h0, h1, h2, h3;
                __nv_bfloat162 hi01 = split_hi2(c[mi][ni][0], c[mi][ni][1], h0, h1);
                __nv_bfloat162 hi23 = split_hi2(c[mi][ni][2], c[mi][ni][3], h2, h3);
                *(__nv_bfloat162*)(Ch + (size_t)row_lo * N + col) = hi01;
                *(__nv_bfloat162*)(Ch + (size_t)(row_lo + 8) * N + col) = hi23;
                *(__nv_bfloat162*)(Cl + (size_t)row_lo * N + col) = __halves2bfloat162(
                    __float2bfloat16(c[mi][ni][0] - __bfloat162float(h0)),
                    __float2bfloat16(c[mi][ni][1] - __bfloat162float(h1)));
                *(__nv_bfloat162*)(Cl + (size_t)(row_lo + 8) * N + col) = __halves2bfloat162(
                    __float2bfloat16(c[mi][ni][2] - __bfloat162float(h2)),
                    __float2bfloat16(c[mi][ni][3] - __bfloat162float(h3)));
            } else {
                *(float2*)(C + (size_t)row_lo * N + col) =
                    make_float2(c[mi][ni][0], c[mi][ni][1]);
                *(float2*)(C + (size_t)(row_lo + 8) * N + col) =
                    make_float2(c[mi][ni][2], c[mi][ni][3]);
            }
        }
    }
}

// ---------------------------------------------------------------------------
// HMMA flash attention (causal) — unchanged from R9 (measured path).
// ---------------------------------------------------------------------------
#define FSTR 72
#define FQH 0
#define FQL (128 * FSTR)
#define FKH (256 * FSTR)
#define FKL (320 * FSTR)
#define FVH (384 * FSTR)
#define FVL (448 * FSTR)
#define F_SMEM_E (512 * FSTR)
#define F_SMEM_BYTES (F_SMEM_E * 2)      // 73728

__global__ __launch_bounds__(256, 2) void flash_hmma_kernel(
    const __nv_bfloat16* __restrict__ qkvh, const __nv_bfloat16* __restrict__ qkvl,
    __nv_bfloat16* __restrict__ outh, __nv_bfloat16* __restrict__ outl)
{
    extern __shared__ __nv_bfloat16 fsm[];
    const uint32_t sm_u = smem_u32(fsm);

    const int qtile = blockIdx.x;
    const int h  = blockIdx.y;
    const int b  = blockIdx.z;
    const int q0 = qtile * 128;

    const int tid = threadIdx.x;
    const int wid = tid >> 5;
    const int lid = tid & 31;
    const int grp = lid >> 2;
    const int qd  = lid & 3;
    const int w16 = wid * 16;

    const size_t base = (size_t)b * T_ * QKV_N + (size_t)h * HD_;
    const __nv_bfloat16* qh_g = qkvh + base;
    const __nv_bfloat16* ql_g = qkvl + base;
    const __nv_bfloat16* kh_g = qkvh + base + D_;
    const __nv_bfloat16* kl_g = qkvl + base + D_;
    const __nv_bfloat16* vh_g = qkvh + base + 2 * D_;
    const __nv_bfloat16* vl_g = qkvl + base + 2 * D_;

    {
#pragma unroll
        for (int i = 0; i < 4; i++) {
            const int idx = tid + i * 256;
            const int r = idx >> 3;
            const int c8 = idx & 7;
            *(uint4*)(fsm + FQH + r * FSTR + c8 * 8) =
                *(const uint4*)(qh_g + (size_t)(q0 + r) * QKV_N + c8 * 8);
            *(uint4*)(fsm + FQL + r * FSTR + c8 * 8) =
                *(const uint4*)(ql_g + (size_t)(q0 + r) * QKV_N + c8 * 8);
        }
    }

    float o[8][4];
#pragma unroll
    for (int ni = 0; ni < 8; ni++)
#pragma unroll
        for (int k = 0; k < 4; k++) o[ni][k] = 0.0f;
    float m0 = -1e30f, m1 = -1e30f, l0 = 0.0f, l1 = 0.0f;

    const uint32_t a_off = (uint32_t)((w16 + (lid & 15)) * FSTR + (lid >> 4) * 8) * 2;
    const uint32_t b_off = (uint32_t)(((lid & 7)) * FSTR + ((lid >> 3) & 1) * 8) * 2;
    const uint32_t v_off = (uint32_t)((lid & 15) * FSTR) * 2;

    const uint32_t uQH = sm_u + FQH * 2, uQL = sm_u + FQL * 2;
    const uint32_t uKH = sm_u + FKH * 2, uKL = sm_u + FKL * 2;
    const uint32_t uVH = sm_u + FVH * 2, uVL = sm_u + FVL * 2;

    const int row0_abs = q0 + w16 + grp;

    auto tile = [&](int kt, bool masked) {
        const int k0 = kt * 64;
        __syncthreads();
        {
#pragma unroll
            for (int i = 0; i < 2; i++) {
                const int idx = tid + i * 256;
                const int r = idx >> 3;
                const int c8 = idx & 7;
                const size_t go = (size_t)(k0 + r) * QKV_N + c8 * 8;
                const int so = r * FSTR + c8 * 8;
                *(uint4*)(fsm + FKH + so) = *(const uint4*)(kh_g + go);
                *(uint4*)(fsm + FKL + so) = *(const uint4*)(kl_g + go);
                *(uint4*)(fsm + FVH + so) = *(const uint4*)(vh_g + go);
                *(uint4*)(fsm + FVL + so) = *(const uint4*)(vl_g + go);
            }
        }
        __syncthreads();

        float s[8][4];
#pragma unroll
        for (int ni = 0; ni < 8; ni++)
#pragma unroll
            for (int k = 0; k < 4; k++) s[ni][k] = 0.0f;

#pragma unroll
        for (int kk4 = 0; kk4 < 4; kk4++) {
            const uint32_t ko = (uint32_t)kk4 * 32;
            uint32_t qh[4], ql[4];
            ldmatrix_x4(qh, uQH + a_off + ko);
            ldmatrix_x4(ql, uQL + a_off + ko);
#pragma unroll
            for (int ni = 0; ni < 8; ni++) {
                const uint32_t no = (uint32_t)(ni * 8 * FSTR) * 2;
                uint32_t kh[2], kl[2];
                ldmatrix_x2(kh, uKH + b_off + no + ko);
                ldmatrix_x2(kl, uKL + b_off + no + ko);
                mma_bf16(s[ni], qh, kh);
                mma_bf16(s[ni], qh, kl);
                mma_bf16(s[ni], ql, kh);
            }
        }

        const float scale = 0.125f;
#pragma unroll
        for (int ni = 0; ni < 8; ni++) {
#pragma unroll
            for (int k = 0; k < 4; k++) s[ni][k] *= scale;
            if (masked) {
                const int col = k0 + ni * 8 + qd * 2;
                if (col > row0_abs)     s[ni][0] = -1e30f;
                if (col + 1 > row0_abs) s[ni][1] = -1e30f;
                if (col > row0_abs + 8)     s[ni][2] = -1e30f;
                if (col + 1 > row0_abs + 8) s[ni][3] = -1e30f;
            }
        }

        float mx0 = -1e30f, mx1 = -1e30f;
#pragma unroll
        for (int ni = 0; ni < 8; ni++) {
            mx0 = fmaxf(mx0, fmaxf(s[ni][0], s[ni][1]));
            mx1 = fmaxf(mx1, fmaxf(s[ni][2], s[ni][3]));
        }
        mx0 = fmaxf(mx0, __shfl_xor_sync(0xffffffffu, mx0, 1));
        mx0 = fmaxf(mx0, __shfl_xor_sync(0xffffffffu, mx0, 2));
        mx1 = fmaxf(mx1, __shfl_xor_sync(0xffffffffu, mx1, 1));
        mx1 = fmaxf(mx1, __shfl_xor_sync(0xffffffffu, mx1, 2));
        const float mn0 = fmaxf(m0, mx0);
        const float mn1 = fmaxf(m1, mx1);
        const float al0 = __expf(m0 - mn0);
        const float al1 = __expf(m1 - mn1);

        uint32_t pH[8][2], pL[8][2];
        float sum0 = 0.0f, sum1 = 0.0f;
#pragma unroll
        for (int ni = 0; ni < 8; ni++) {
            float p0 = __expf(s[ni][0] - mn0);
            float p1 = __expf(s[ni][1] - mn0);
            float p2 = __expf(s[ni][2] - mn1);
            float p3 = __expf(s[ni][3] - mn1);
            sum0 += p0 + p1; sum1 += p2 + p3;
            __nv_bfloat16 h0, h1, h2, h3;
            __nv_bfloat162 ph01 = split_hi2(p0, p1, h0, h1);
            __nv_bfloat162 ph23 = split_hi2(p2, p3, h2, h3);
            __nv_bfloat162 pl01 = __halves2bfloat162(
                __float2bfloat16(p0 - __bfloat162float(h0)),
                __float2bfloat16(p1 - __bfloat162float(h1)));
            __nv_bfloat162 pl23 = __halves2bfloat162(
                __float2bfloat16(p2 - __bfloat162float(h2)),
                __float2bfloat16(p3 - __bfloat162float(h3)));
            pH[ni][0] = *(uint32_t*)&ph01; pH[ni][1] = *(uint32_t*)&ph23;
            pL[ni][0] = *(uint32_t*)&pl01; pL[ni][1] = *(uint32_t*)&pl23;
        }
        sum0 += __shfl_xor_sync(0xffffffffu, sum0, 1);
        sum0 += __shfl_xor_sync(0xffffffffu, sum0, 2);
        sum1 += __shfl_xor_sync(0xffffffffu, sum1, 1);
        sum1 += __shfl_xor_sync(0xffffffffu, sum1, 2);
        l0 = l0 * al0 + sum0;
        l1 = l1 * al1 + sum1;
        m0 = mn0; m1 = mn1;
#pragma unroll
        for (int ni = 0; ni < 8; ni++) {
            o[ni][0] *= al0; o[ni][1] *= al0;
            o[ni][2] *= al1; o[ni][3] *= al1;
        }

#pragma unroll
        for (int j = 0; j < 4; j++) {
            uint32_t ah[4] = { pH[2 * j][0], pH[2 * j][1], pH[2 * j + 1][0], pH[2 * j + 1][1] };
            uint32_t al_[4] = { pL[2 * j][0], pL[2 * j][1], pL[2 * j + 1][0], pL[2 * j + 1][1] };
            const uint32_t jo = (uint32_t)(j * 16 * FSTR) * 2;
#pragma unroll
            for (int ni = 0; ni < 8; ni++) {
                const uint32_t no = (uint32_t)(ni * 8) * 2;
                uint32_t vh[2], vl[2];
                ldmatrix_x2_trans(vh, uVH + v_off + jo + no);
                ldmatrix_x2_trans(vl, uVL + v_off + jo + no);
                mma_bf16(o[ni], ah, vh);
                mma_bf16(o[ni], al_, vh);
                mma_bf16(o[ni], ah, vl);
            }
        }
    };

    for (int kt = 0; kt < 2 * qtile; kt++) tile(kt, false);
    tile(2 * qtile, true);
    tile(2 * qtile + 1, true);

    const float inv0 = 1.0f / l0;
    const float inv1 = 1.0f / l1;
    const size_t ro0 = (size_t)(b * T_ + row0_abs) * D_ + h * HD_;
    const size_t ro1 = ro0 + (size_t)8 * D_;
#pragma unroll
    for (int ni = 0; ni < 8; ni++) {
        float v0 = o[ni][0] * inv0, v1 = o[ni][1] * inv0;
        float v2 = o[ni][2] * inv1, v3 = o[ni][3] * inv1;
        __nv_bfloat16 h0, h1, h2, h3;
        __nv_bfloat162 hi01 = split_hi2(v0, v1, h0, h1);
        __nv_bfloat162 hi23 = split_hi2(v2, v3, h2, h3);
        *(__nv_bfloat162*)(outh + ro0 + ni * 8 + qd * 2) = hi01;
        *(__nv_bfloat162*)(outh + ro1 + ni * 8 + qd * 2) = hi23;
        *(__nv_bfloat162*)(outl + ro0 + ni * 8 + qd * 2) = __halves2bfloat162(
            __float2bfloat16(v0 - __bfloat162float(h0)),
            __float2bfloat16(v1 - __bfloat162float(h1)));
        *(__nv_bfloat162*)(outl + ro1 + ni * 8 + qd * 2) = __halves2bfloat162(
            __float2bfloat16(v2 - __bfloat162float(h2)),
            __float2bfloat16(v3 - __bfloat162float(h3)));
    }
}

// ---------------------------------------------------------------------------
// kernel_launch
// ---------------------------------------------------------------------------
extern "C" void kernel_launch(void* const* d_in, const int* in_sizes, int n_in,
                              void* d_out, int out_size)
{
    const float* x     = (const float*)d_in[0];
    const float* w_qkv = (const float*)d_in[1];
    const float* w_out = (const float*)d_in[2];
    float* out = (float*)d_out;

    __nv_bfloat16 *qkvh, *qkvl, *xh, *xl, *ah, *al, *wqh, *wql, *woh, *wol;
    cudaGetSymbolAddress((void**)&qkvh, g_qkvh);
    cudaGetSymbolAddress((void**)&qkvl, g_qkvl);
    cudaGetSymbolAddress((void**)&xh,  g_xh);
    cudaGetSymbolAddress((void**)&xl,  g_xl);
    cudaGetSymbolAddress((void**)&ah,  g_ah);
    cudaGetSymbolAddress((void**)&al,  g_al);
    cudaGetSymbolAddress((void**)&wqh, g_wqh);
    cudaGetSymbolAddress((void**)&wql, g_wql);
    cudaGetSymbolAddress((void**)&woh, g_woh);
    cudaGetSymbolAddress((void**)&wol, g_wol);

    cudaFuncSetAttribute(hmma_gemm_kernel<true>,
                         cudaFuncAttributeMaxDynamicSharedMemorySize, MSMEM_TOTAL);
    cudaFuncSetAttribute(hmma_gemm_kernel<false>,
                         cudaFuncAttributeMaxDynamicSharedMemorySize, MSMEM_TOTAL);
    cudaFuncSetAttribute(flash_hmma_kernel,
                         cudaFuncAttributeMaxDynamicSharedMemorySize, F_SMEM_BYTES);

    {
        int n4 = BT_ * D_ / 4;
        convert_split_kernel<<<(n4 + 255) / 256, 256>>>(x, xh, xl, n4);
    }
    {
        dim3 bb(32, 8);
        transpose_split_kernel<<<dim3(QKV_N / 32, D_ / 32), bb>>>(w_qkv, wqh, wql, D_, QKV_N);
        transpose_split_kernel<<<dim3(D_ / 32,   D_ / 32), bb>>>(w_out, woh, wol, D_, D_);
    }
    {
        dim3 g(QKV_N / MBN, BT_ / MBM);   // (24, 64)
        hmma_gemm_kernel<true><<<g, 256, MSMEM_TOTAL>>>(
            xh, xl, wqh, wql, nullptr, qkvh, qkvl, BT_, QKV_N, D_);
    }
    {
        dim3 g(T_ / 128, H_, B_);
        flash_hmma_kernel<<<g, 256, F_SMEM_BYTES>>>(qkvh, qkvl, ah, al);
    }
    {
        dim3 g(D_ / MBN, BT_ / MBM);      // (8, 64)
        hmma_gemm_kernel<false><<<g, 256, MSMEM_TOTAL>>>(
            ah, al, woh, wol, out, nullptr, nullptr, BT_, D_, D_);
    }
}

// round 14
// speedup vs baseline: 1.5459x; 1.5092x over previous
#include <cuda_runtime.h>
#include <cuda_bf16.h>
#include <cstdint>
#include <math.h>

#define B_  4
#define T_  2048
#define D_  1024
#define H_  16
#define HD_ 64
#define BT_ (B_ * T_)            // 8192
#define QKV_N (3 * D_)           // 3072

// ---------------------------------------------------------------------------
// Scratch (allocation-free rule: __device__ globals)
// ---------------------------------------------------------------------------
__device__ __nv_bfloat16 g_qkvh[(size_t)BT_ * QKV_N];
__device__ __nv_bfloat16 g_qkvl[(size_t)BT_ * QKV_N];
__device__ __nv_bfloat16 g_xh[(size_t)BT_ * D_];
__device__ __nv_bfloat16 g_xl[(size_t)BT_ * D_];
__device__ __nv_bfloat16 g_ah[(size_t)BT_ * D_];
__device__ __nv_bfloat16 g_al[(size_t)BT_ * D_];
__device__ __nv_bfloat16 g_wqh[(size_t)QKV_N * D_];
__device__ __nv_bfloat16 g_wql[(size_t)QKV_N * D_];
__device__ __nv_bfloat16 g_woh[(size_t)D_ * D_];
__device__ __nv_bfloat16 g_wol[(size_t)D_ * D_];

// ---------------------------------------------------------------------------
// helpers (sm_80-level PTX, valid at sm_103)
// ---------------------------------------------------------------------------
__device__ __forceinline__ uint32_t smem_u32(const void* p) {
    uint32_t a;
    asm("{ .reg .u64 t; cvta.to.shared.u64 t, %1; cvt.u32.u64 %0, t; }"
        : "=r"(a) : "l"(p));
    return a;
}
__device__ __forceinline__ void ldmatrix_x4(uint32_t* r, uint32_t addr) {
    asm volatile("ldmatrix.sync.aligned.m8n8.x4.shared.b16 {%0,%1,%2,%3}, [%4];"
        : "=r"(r[0]), "=r"(r[1]), "=r"(r[2]), "=r"(r[3]) : "r"(addr));
}
__device__ __forceinline__ void ldmatrix_x2(uint32_t* r, uint32_t addr) {
    asm volatile("ldmatrix.sync.aligned.m8n8.x2.shared.b16 {%0,%1}, [%2];"
        : "=r"(r[0]), "=r"(r[1]) : "r"(addr));
}
__device__ __forceinline__ void ldmatrix_x2_trans(uint32_t* r, uint32_t addr) {
    asm volatile("ldmatrix.sync.aligned.m8n8.x2.trans.shared.b16 {%0,%1}, [%2];"
        : "=r"(r[0]), "=r"(r[1]) : "r"(addr));
}
__device__ __forceinline__ void mma_bf16(float* c, const uint32_t* a, const uint32_t* b) {
    asm volatile(
        "mma.sync.aligned.m16n8k16.row.col.f32.bf16.bf16.f32 "
        "{%0,%1,%2,%3}, {%4,%5,%6,%7}, {%8,%9}, {%0,%1,%2,%3};"
        : "+f"(c[0]), "+f"(c[1]), "+f"(c[2]), "+f"(c[3])
        : "r"(a[0]), "r"(a[1]), "r"(a[2]), "r"(a[3]), "r"(b[0]), "r"(b[1]));
}
__device__ __forceinline__ void cp16(uint32_t dst, const void* src) {
    asm volatile("cp.async.cg.shared.global [%0], [%1], 16;" :: "r"(dst), "l"(src));
}
__device__ __forceinline__ void cp_commit() {
    asm volatile("cp.async.commit_group;" ::: "memory");
}
__device__ __forceinline__ void cp_wait1() {
    asm volatile("cp.async.wait_group 1;" ::: "memory");
}
__device__ __forceinline__ __nv_bfloat162 split_hi2(float a, float b,
                                                    __nv_bfloat16& ha, __nv_bfloat16& hb) {
    ha = __float2bfloat16(a); hb = __float2bfloat16(b);
    return __halves2bfloat162(ha, hb);
}

// ---------------------------------------------------------------------------
// Split fp32 -> bf16 hi/lo
// ---------------------------------------------------------------------------
__global__ __launch_bounds__(256) void convert_split_kernel(
    const float* __restrict__ in, __nv_bfloat16* __restrict__ hi,
    __nv_bfloat16* __restrict__ lo, int n4)
{
    int i = blockIdx.x * blockDim.x + threadIdx.x;
    if (i >= n4) return;
    float4 v = ((const float4*)in)[i];
    __nv_bfloat16 h0 = __float2bfloat16(v.x);
    __nv_bfloat16 h1 = __float2bfloat16(v.y);
    __nv_bfloat16 h2 = __float2bfloat16(v.z);
    __nv_bfloat16 h3 = __float2bfloat16(v.w);
    __nv_bfloat162* hp = (__nv_bfloat162*)hi;
    __nv_bfloat162* lp = (__nv_bfloat162*)lo;
    hp[2 * i]     = __halves2bfloat162(h0, h1);
    hp[2 * i + 1] = __halves2bfloat162(h2, h3);
    lp[2 * i]     = __halves2bfloat162(
        __float2bfloat16(v.x - __bfloat162float(h0)),
        __float2bfloat16(v.y - __bfloat162float(h1)));
    lp[2 * i + 1] = __halves2bfloat162(
        __float2bfloat16(v.z - __bfloat162float(h2)),
        __float2bfloat16(v.w - __bfloat162float(h3)));
}

// ---------------------------------------------------------------------------
// Transpose W[K,N] fp32 -> Bh/Bl[N,K] bf16 (hi/lo split)
// ---------------------------------------------------------------------------
__global__ __launch_bounds__(256) void transpose_split_kernel(
    const float* __restrict__ w, __nv_bfloat16* __restrict__ bh,
    __nv_bfloat16* __restrict__ bl, int K, int N)
{
    __shared__ float t[32][33];
    const int n0 = blockIdx.x * 32;
    const int k0 = blockIdx.y * 32;
    const int tx = threadIdx.x;
    const int ty = threadIdx.y;
#pragma unroll
    for (int i = 0; i < 32; i += 8)
        t[ty + i][tx] = w[(size_t)(k0 + ty + i) * N + n0 + tx];
    __syncthreads();
#pragma unroll
    for (int i = 0; i < 32; i += 8) {
        float v = t[tx][ty + i];
        __nv_bfloat16 h = __float2bfloat16(v);
        __nv_bfloat16 l = __float2bfloat16(v - __bfloat162float(h));
        bh[(size_t)(n0 + ty + i) * K + k0 + tx] = h;
        bl[(size_t)(n0 + ty + i) * K + k0 + tx] = l;
    }
}

// ---------------------------------------------------------------------------
// HMMA GEMM — EXACT R9 config (measured best: 460us QKV).
// cp.async 2-stage, 256 threads (8 warps), warp tile 64x32, BK=64.
// 3-term bf16 split: AhBh + AhBl + AlBh, fp32 accum.
// ---------------------------------------------------------------------------
#define MBM 128
#define MBN 128
#define MBK 64
#define MSTRIDE 72
#define MTILE_E (128 * MSTRIDE)
#define MSTG_E  (4 * MTILE_E)
#define MSMEM_TOTAL (2 * MSTG_E * 2)     // 147456 bytes

template <bool SPLIT_OUT>
__global__ __launch_bounds__(256) void hmma_gemm_kernel(
    const __nv_bfloat16* __restrict__ Ah, const __nv_bfloat16* __restrict__ Al,
    const __nv_bfloat16* __restrict__ Bh, const __nv_bfloat16* __restrict__ Bl,
    float* __restrict__ C,
    __nv_bfloat16* __restrict__ Ch, __nv_bfloat16* __restrict__ Cl,
    int M, int N, int K)
{
    extern __shared__ __nv_bfloat16 sm[];
    const uint32_t sm_u = smem_u32(sm);

    const int tid = threadIdx.x;
    const int wid = tid >> 5;
    const int lid = tid & 31;
    const int bm  = blockIdx.y * MBM;
    const int bn  = blockIdx.x * MBN;
    const int wr  = wid >> 2;
    const int wc  = wid & 3;

    float c[4][4][4];
#pragma unroll
    for (int mi = 0; mi < 4; mi++)
#pragma unroll
        for (int ni = 0; ni < 4; ni++)
#pragma unroll
            for (int k = 0; k < 4; k++) c[mi][ni][k] = 0.0f;

    const int r0  = tid >> 3;
    const int c16 = tid & 7;
    const uint32_t sm_off = (uint32_t)(r0 * 144 + c16 * 16);

    const __nv_bfloat16* gsrc[4] = {
        Ah + (size_t)(bm + r0) * K + c16 * 8,
        Al + (size_t)(bm + r0) * K + c16 * 8,
        Bh + (size_t)(bn + r0) * K + c16 * 8,
        Bl + (size_t)(bn + r0) * K + c16 * 8 };

    auto issue_chunk = [&](int ch, int stage) {
        const uint32_t sbase = sm_u + (uint32_t)stage * (MSTG_E * 2);
        const int k0 = ch * MBK;
#pragma unroll
        for (int t = 0; t < 4; t++) {
            const __nv_bfloat16* g = gsrc[t] + k0;
            const uint32_t sb = sbase + (uint32_t)t * (MTILE_E * 2) + sm_off;
#pragma unroll
            for (int i = 0; i < 4; i++)
                cp16(sb + (uint32_t)i * (32 * 144), g + (size_t)(32 * i) * K);
        }
    };

    const int a_row = wr * 64 + (lid & 15);
    const int a_col = (lid >> 4) * 8;
    const int b_row = wc * 32 + (lid & 7);
    const int b_col = ((lid >> 3) & 1) * 8;
    const uint32_t a_off = (uint32_t)(a_row * MSTRIDE + a_col) * 2;
    const uint32_t b_off = (uint32_t)(b_row * MSTRIDE + b_col) * 2;

    const int nch = K / MBK;
    issue_chunk(0, 0);
    cp_commit();

    for (int ch = 0; ch < nch; ch++) {
        const int s = ch & 1;
        if (ch + 1 < nch) issue_chunk(ch + 1, s ^ 1);
        cp_commit();
        cp_wait1();
        __syncthreads();

        const uint32_t st = sm_u + (uint32_t)s * (MSTG_E * 2);
        const uint32_t uAh = st;
        const uint32_t uAl = st + MTILE_E * 2;
        const uint32_t uBh = st + 2 * MTILE_E * 2;
        const uint32_t uBl = st + 3 * MTILE_E * 2;

#pragma unroll
        for (int kk = 0; kk < MBK; kk += 16) {
            uint32_t af[4][4], bf[4][2];
#pragma unroll
            for (int mi = 0; mi < 4; mi++)
                ldmatrix_x4(af[mi], uAh + a_off + (uint32_t)(mi * 16 * MSTRIDE + kk) * 2);
#pragma unroll
            for (int ni = 0; ni < 4; ni++)
                ldmatrix_x2(bf[ni], uBh + b_off + (uint32_t)(ni * 8 * MSTRIDE + kk) * 2);
#pragma unroll
            for (int mi = 0; mi < 4; mi++)
#pragma unroll
                for (int ni = 0; ni < 4; ni++)
                    mma_bf16(c[mi][ni], af[mi], bf[ni]);
            uint32_t bl_[4][2];
#pragma unroll
            for (int ni = 0; ni < 4; ni++)
                ldmatrix_x2(bl_[ni], uBl + b_off + (uint32_t)(ni * 8 * MSTRIDE + kk) * 2);
#pragma unroll
            for (int mi = 0; mi < 4; mi++)
#pragma unroll
                for (int ni = 0; ni < 4; ni++)
                    mma_bf16(c[mi][ni], af[mi], bl_[ni]);
#pragma unroll
            for (int mi = 0; mi < 4; mi++)
                ldmatrix_x4(af[mi], uAl + a_off + (uint32_t)(mi * 16 * MSTRIDE + kk) * 2);
#pragma unroll
            for (int mi = 0; mi < 4; mi++)
#pragma unroll
                for (int ni = 0; ni < 4; ni++)
                    mma_bf16(c[mi][ni], af[mi], bf[ni]);
        }
        __syncthreads();
    }

    const int grp = lid >> 2;
    const int qd  = lid & 3;
#pragma unroll
    for (int mi = 0; mi < 4; mi++) {
        const int row_lo = bm + wr * 64 + mi * 16 + grp;
#pragma unroll
        for (int ni = 0; ni < 4; ni++) {
            const int col = bn + wc * 32 + ni * 8 + qd * 2;
            if (SPLIT_OUT) {
                __nv_bfloat16 h0, h1, h2, h3;
                __nv_bfloat162 hi01 = split_hi2(c[mi][ni][0], c[mi][ni][1], h0, h1);
                __nv_bfloat162 hi23 = split_hi2(c[mi][ni][2], c[mi][ni][3], h2, h3);
                *(__nv_bfloat162*)(Ch + (size_t)row_lo * N + col) = hi01;
                *(__nv_bfloat162*)(Ch + (size_t)(row_lo + 8) * N + col) = hi23;
                *(__nv_bfloat162*)(Cl + (size_t)row_lo * N + col) = __halves2bfloat162(
                    __float2bfloat16(c[mi][ni][0] - __bfloat162float(h0)),
                    __float2bfloat16(c[mi][ni][1] - __bfloat162float(h1)));
                *(__nv_bfloat162*)(Cl + (size_t)(row_lo + 8) * N + col) = __halves2bfloat162(
                    __float2bfloat16(c[mi][ni][2] - __bfloat162float(h2)),
                    __float2bfloat16(c[mi][ni][3] - __bfloat162float(h3)));
            } else {
                *(float2*)(C + (size_t)row_lo * N + col) =
                    make_float2(c[mi][ni][0], c[mi][ni][1]);
                *(float2*)(C + (size_t)(row_lo + 8) * N + col) =
                    make_float2(c[mi][ni][2], c[mi][ni][3]);
            }
        }
    }
}

// ---------------------------------------------------------------------------
// HMMA flash attention (causal), cp.async 2-stage K/V pipeline.
// BM=128, BN=64, HD=64, 8 warps. Math identical to R9.
// cp.async coverage (FIXED): per sub-tile 64 rows x 8 16B-cols = 512 chunks;
// 256 threads x 2 rows (kvr, kvr+32) = 512.  256*2 == 64*8  ✓
// ---------------------------------------------------------------------------
#define FSTR 72
#define FQH 0
#define FQL (128 * FSTR)                  // 9216
#define FKV0 (256 * FSTR)                 // 18432: start of stage 0
#define FKV_STG (4 * 64 * FSTR)           // 18432 elems per stage
#define FKV_T (64 * FSTR)                 // 4608 elems per sub-tile
#define F_SMEM_E (FKV0 + 2 * FKV_STG)     // 55296 elems
#define F_SMEM_BYTES (F_SMEM_E * 2)       // 110592 bytes

__global__ __launch_bounds__(256, 2) void flash_hmma_kernel(
    const __nv_bfloat16* __restrict__ qkvh, const __nv_bfloat16* __restrict__ qkvl,
    __nv_bfloat16* __restrict__ outh, __nv_bfloat16* __restrict__ outl)
{
    extern __shared__ __nv_bfloat16 fsm[];
    const uint32_t sm_u = smem_u32(fsm);

    const int qtile = blockIdx.x;
    const int h  = blockIdx.y;
    const int b  = blockIdx.z;
    const int q0 = qtile * 128;

    const int tid = threadIdx.x;
    const int wid = tid >> 5;
    const int lid = tid & 31;
    const int grp = lid >> 2;
    const int qd  = lid & 3;
    const int w16 = wid * 16;

    const size_t base = (size_t)b * T_ * QKV_N + (size_t)h * HD_;
    const __nv_bfloat16* qh_g = qkvh + base;
    const __nv_bfloat16* ql_g = qkvl + base;
    const __nv_bfloat16* kh_g = qkvh + base + D_;
    const __nv_bfloat16* kl_g = qkvl + base + D_;
    const __nv_bfloat16* vh_g = qkvh + base + 2 * D_;
    const __nv_bfloat16* vl_g = qkvl + base + 2 * D_;

    // ---- load Q tile (128x64 hi+lo) ----
    {
#pragma unroll
        for (int i = 0; i < 4; i++) {
            const int idx = tid + i * 256;
            const int r = idx >> 3;
            const int c8 = idx & 7;
            *(uint4*)(fsm + FQH + r * FSTR + c8 * 8) =
                *(const uint4*)(qh_g + (size_t)(q0 + r) * QKV_N + c8 * 8);
            *(uint4*)(fsm + FQL + r * FSTR + c8 * 8) =
                *(const uint4*)(ql_g + (size_t)(q0 + r) * QKV_N + c8 * 8);
        }
    }

    float o[8][4];
#pragma unroll
    for (int ni = 0; ni < 8; ni++)
#pragma unroll
        for (int k = 0; k < 4; k++) o[ni][k] = 0.0f;
    float m0 = -1e30f, m1 = -1e30f, l0 = 0.0f, l1 = 0.0f;

    const uint32_t a_off = (uint32_t)((w16 + (lid & 15)) * FSTR + (lid >> 4) * 8) * 2;
    const uint32_t b_off = (uint32_t)(((lid & 7)) * FSTR + ((lid >> 3) & 1) * 8) * 2;
    const uint32_t v_off = (uint32_t)((lid & 15) * FSTR) * 2;

    const uint32_t uQH = sm_u + FQH * 2, uQL = sm_u + FQL * 2;

    const int row0_abs = q0 + w16 + grp;

    // cp.async mapping (fixed): rows kvr and kvr+32, 16B column kvc (8 cols/row)
    const int kvr  = tid >> 3;            // 0..31
    const int kvc  = tid & 7;             // 0..7
    const uint32_t kv_so = (uint32_t)(kvr * 144 + kvc * 16);

    auto issue_kv = [&](int kt, int stage) {
        const int k0 = kt * 64;
        const uint32_t sb = sm_u + (uint32_t)(FKV0 + stage * FKV_STG) * 2 + kv_so;
        const size_t go  = (size_t)(k0 + kvr) * QKV_N + kvc * 8;
        const size_t go2 = go + (size_t)32 * QKV_N;
        const uint32_t sb2 = sb + (uint32_t)(32 * 144);
        cp16(sb,                          kh_g + go);
        cp16(sb2,                         kh_g + go2);
        cp16(sb  + (uint32_t)FKV_T * 2,   kl_g + go);
        cp16(sb2 + (uint32_t)FKV_T * 2,   kl_g + go2);
        cp16(sb  + (uint32_t)FKV_T * 4,   vh_g + go);
        cp16(sb2 + (uint32_t)FKV_T * 4,   vh_g + go2);
        cp16(sb  + (uint32_t)FKV_T * 6,   vl_g + go);
        cp16(sb2 + (uint32_t)FKV_T * 6,   vl_g + go2);
    };

    auto compute = [&](int kt, int stage, bool masked) {
        const int k0 = kt * 64;
        const uint32_t st = sm_u + (uint32_t)(FKV0 + stage * FKV_STG) * 2;
        const uint32_t uKH = st;
        const uint32_t uKL = st + (uint32_t)FKV_T * 2;
        const uint32_t uVH = st + (uint32_t)FKV_T * 4;
        const uint32_t uVL = st + (uint32_t)FKV_T * 6;

        float s[8][4];
#pragma unroll
        for (int ni = 0; ni < 8; ni++)
#pragma unroll
            for (int k = 0; k < 4; k++) s[ni][k] = 0.0f;

#pragma unroll
        for (int kk4 = 0; kk4 < 4; kk4++) {
            const uint32_t ko = (uint32_t)kk4 * 32;
            uint32_t qh[4], ql[4];
            ldmatrix_x4(qh, uQH + a_off + ko);
            ldmatrix_x4(ql, uQL + a_off + ko);
#pragma unroll
            for (int ni = 0; ni < 8; ni++) {
                const uint32_t no = (uint32_t)(ni * 8 * FSTR) * 2;
                uint32_t kh[2], kl[2];
                ldmatrix_x2(kh, uKH + b_off + no + ko);
                ldmatrix_x2(kl, uKL + b_off + no + ko);
                mma_bf16(s[ni], qh, kh);
                mma_bf16(s[ni], qh, kl);
                mma_bf16(s[ni], ql, kh);
            }
        }

        const float scale = 0.125f;
#pragma unroll
        for (int ni = 0; ni < 8; ni++) {
#pragma unroll
            for (int k = 0; k < 4; k++) s[ni][k] *= scale;
            if (masked) {
                const int col = k0 + ni * 8 + qd * 2;
                if (col > row0_abs)     s[ni][0] = -1e30f;
                if (col + 1 > row0_abs) s[ni][1] = -1e30f;
                if (col > row0_abs + 8)     s[ni][2] = -1e30f;
                if (col + 1 > row0_abs + 8) s[ni][3] = -1e30f;
            }
        }

        float mx0 = -1e30f, mx1 = -1e30f;
#pragma unroll
        for (int ni = 0; ni < 8; ni++) {
            mx0 = fmaxf(mx0, fmaxf(s[ni][0], s[ni][1]));
            mx1 = fmaxf(mx1, fmaxf(s[ni][2], s[ni][3]));
        }
        mx0 = fmaxf(mx0, __shfl_xor_sync(0xffffffffu, mx0, 1));
        mx0 = fmaxf(mx0, __shfl_xor_sync(0xffffffffu, mx0, 2));
        mx1 = fmaxf(mx1, __shfl_xor_sync(0xffffffffu, mx1, 1));
        mx1 = fmaxf(mx1, __shfl_xor_sync(0xffffffffu, mx1, 2));
        const float mn0 = fmaxf(m0, mx0);
        const float mn1 = fmaxf(m1, mx1);
        const float al0 = __expf(m0 - mn0);
        const float al1 = __expf(m1 - mn1);

        uint32_t pH[8][2], pL[8][2];
        float sum0 = 0.0f, sum1 = 0.0f;
#pragma unroll
        for (int ni = 0; ni < 8; ni++) {
            float p0 = __expf(s[ni][0] - mn0);
            float p1 = __expf(s[ni][1] - mn0);
            float p2 = __expf(s[ni][2] - mn1);
            float p3 = __expf(s[ni][3] - mn1);
            sum0 += p0 + p1; sum1 += p2 + p3;
            __nv_bfloat16 h0, h1, h2, h3;
            __nv_bfloat162 ph01 = split_hi2(p0, p1, h0, h1);
            __nv_bfloat162 ph23 = split_hi2(p2, p3, h2, h3);
            __nv_bfloat162 pl01 = __halves2bfloat162(
                __float2bfloat16(p0 - __bfloat162float(h0)),
                __float2bfloat16(p1 - __bfloat162float(h1)));
            __nv_bfloat162 pl23 = __halves2bfloat162(
                __float2bfloat16(p2 - __bfloat162float(h2)),
                __float2bfloat16(p3 - __bfloat162float(h3)));
            pH[ni][0] = *(uint32_t*)&ph01; pH[ni][1] = *(uint32_t*)&ph23;
            pL[ni][0] = *(uint32_t*)&pl01; pL[ni][1] = *(uint32_t*)&pl23;
        }
        sum0 += __shfl_xor_sync(0xffffffffu, sum0, 1);
        sum0 += __shfl_xor_sync(0xffffffffu, sum0, 2);
        sum1 += __shfl_xor_sync(0xffffffffu, sum1, 1);
        sum1 += __shfl_xor_sync(0xffffffffu, sum1, 2);
        l0 = l0 * al0 + sum0;
        l1 = l1 * al1 + sum1;
        m0 = mn0; m1 = mn1;
#pragma unroll
        for (int ni = 0; ni < 8; ni++) {
            o[ni][0] *= al0; o[ni][1] *= al0;
            o[ni][2] *= al1; o[ni][3] *= al1;
        }

#pragma unroll
        for (int j = 0; j < 4; j++) {
            uint32_t ah[4] = { pH[2 * j][0], pH[2 * j][1], pH[2 * j + 1][0], pH[2 * j + 1][1] };
            uint32_t al_[4] = { pL[2 * j][0], pL[2 * j][1], pL[2 * j + 1][0], pL[2 * j + 1][1] };
            const uint32_t jo = (uint32_t)(j * 16 * FSTR) * 2;
#pragma unroll
            for (int ni = 0; ni < 8; ni++) {
                const uint32_t no = (uint32_t)(ni * 8) * 2;
                uint32_t vh[2], vl[2];
                ldmatrix_x2_trans(vh, uVH + v_off + jo + no);
                ldmatrix_x2_trans(vl, uVL + v_off + jo + no);
                mma_bf16(o[ni], ah, vh);
                mma_bf16(o[ni], al_, vh);
                mma_bf16(o[ni], ah, vl);
            }
        }
    };

    const int nt = 2 * qtile + 2;
    issue_kv(0, 0);
    cp_commit();
    for (int kt = 0; kt < nt; kt++) {
        const int s = kt & 1;
        if (kt + 1 < nt) issue_kv(kt + 1, s ^ 1);
        cp_commit();
        cp_wait1();
        __syncthreads();
        compute(kt, s, kt >= 2 * qtile);
        __syncthreads();
    }

    const float inv0 = 1.0f / l0;
    const float inv1 = 1.0f / l1;
    const size_t ro0 = (size_t)(b * T_ + row0_abs) * D_ + h * HD_;
    const size_t ro1 = ro0 + (size_t)8 * D_;
#pragma unroll
    for (int ni = 0; ni < 8; ni++) {
        float v0 = o[ni][0] * inv0, v1 = o[ni][1] * inv0;
        float v2 = o[ni][2] * inv1, v3 = o[ni][3] * inv1;
        __nv_bfloat16 h0, h1, h2, h3;
        __nv_bfloat162 hi01 = split_hi2(v0, v1, h0, h1);
        __nv_bfloat162 hi23 = split_hi2(v2, v3, h2, h3);
        *(__nv_bfloat162*)(outh + ro0 + ni * 8 + qd * 2) = hi01;
        *(__nv_bfloat162*)(outh + ro1 + ni * 8 + qd * 2) = hi23;
        *(__nv_bfloat162*)(outl + ro0 + ni * 8 + qd * 2) = __halves2bfloat162(
            __float2bfloat16(v0 - __bfloat162float(h0)),
            __float2bfloat16(v1 - __bfloat162float(h1)));
        *(__nv_bfloat162*)(outl + ro1 + ni * 8 + qd * 2) = __halves2bfloat162(
            __float2bfloat16(v2 - __bfloat162float(h2)),
            __float2bfloat16(v3 - __bfloat162float(h3)));
    }
}

// ---------------------------------------------------------------------------
// kernel_launch
// ---------------------------------------------------------------------------
extern "C" void kernel_launch(void* const* d_in, const int* in_sizes, int n_in,
                              void* d_out, int out_size)
{
    const float* x     = (const float*)d_in[0];
    const float* w_qkv = (const float*)d_in[1];
    const float* w_out = (const float*)d_in[2];
    float* out = (float*)d_out;

    __nv_bfloat16 *qkvh, *qkvl, *xh, *xl, *ah, *al, *wqh, *wql, *woh, *wol;
    cudaGetSymbolAddress((void**)&qkvh, g_qkvh);
    cudaGetSymbolAddress((void**)&qkvl, g_qkvl);
    cudaGetSymbolAddress((void**)&xh,  g_xh);
    cudaGetSymbolAddress((void**)&xl,  g_xl);
    cudaGetSymbolAddress((void**)&ah,  g_ah);
    cudaGetSymbolAddress((void**)&al,  g_al);
    cudaGetSymbolAddress((void**)&wqh, g_wqh);
    cudaGetSymbolAddress((void**)&wql, g_wql);
    cudaGetSymbolAddress((void**)&woh, g_woh);
    cudaGetSymbolAddress((void**)&wol, g_wol);

    cudaFuncSetAttribute(hmma_gemm_kernel<true>,
                         cudaFuncAttributeMaxDynamicSharedMemorySize, MSMEM_TOTAL);
    cudaFuncSetAttribute(hmma_gemm_kernel<false>,
                         cudaFuncAttributeMaxDynamicSharedMemorySize, MSMEM_TOTAL);
    cudaFuncSetAttribute(flash_hmma_kernel,
                         cudaFuncAttributeMaxDynamicSharedMemorySize, F_SMEM_BYTES);

    {
        int n4 = BT_ * D_ / 4;
        convert_split_kernel<<<(n4 + 255) / 256, 256>>>(x, xh, xl, n4);
    }
    {
        dim3 bb(32, 8);
        transpose_split_kernel<<<dim3(QKV_N / 32, D_ / 32), bb>>>(w_qkv, wqh, wql, D_, QKV_N);
        transpose_split_kernel<<<dim3(D_ / 32,   D_ / 32), bb>>>(w_out, woh, wol, D_, D_);
    }
    {
        dim3 g(QKV_N / MBN, BT_ / MBM);   // (24, 64)
        hmma_gemm_kernel<true><<<g, 256, MSMEM_TOTAL>>>(
            xh, xl, wqh, wql, nullptr, qkvh, qkvl, BT_, QKV_N, D_);
    }
    {
        dim3 g(T_ / 128, H_, B_);
        flash_hmma_kernel<<<g, 256, F_SMEM_BYTES>>>(qkvh, qkvl, ah, al);
    }
    {
        dim3 g(D_ / MBN, BT_ / MBM);      // (8, 64)
        hmma_gemm_kernel<false><<<g, 256, MSMEM_TOTAL>>>(
            ah, al, woh, wol, out, nullptr, nullptr, BT_, D_, D_);
    }
}